// round 1
// baseline (speedup 1.0000x reference)
#include <cuda_runtime.h>

// TtLlamaRotary: per-position rotation.
//   xq      [1, 8, 128, 128]  (d_in[0])
//   xk      [1, 1, 128, 128]  (d_in[1])
//   rot_mat [1, 128, 128, 128] (d_in[2])
// out = concat(xq_out [8,128,128], xk_out [1,128,128]) flat float32.
//
// One CTA per seq position s. 128 threads; thread t owns output column d=t.
// Stage the 9 input rows (8 q heads + 1 k head) for this position in smem,
// then stream R_s row-by-row: acc[n] += xs[n][h] * R[h][t].

#define SEQ_LEN 128
#define HEAD_DIM 128
#define NQ 8
#define NROWS 9  // 8 q heads + 1 k head

__global__ __launch_bounds__(HEAD_DIM, 8)
void rotary_kernel(const float* __restrict__ xq,
                   const float* __restrict__ xk,
                   const float* __restrict__ rot,
                   float* __restrict__ out) {
    const int s = blockIdx.x;   // seq position
    const int t = threadIdx.x;  // output dim d

    __shared__ float xs[NROWS][HEAD_DIM];

    // Load the 9 input rows for this position.
    #pragma unroll
    for (int n = 0; n < NQ; n++)
        xs[n][t] = xq[(n * SEQ_LEN + s) * HEAD_DIM + t];
    xs[NQ][t] = xk[s * HEAD_DIM + t];
    __syncthreads();

    const float* __restrict__ R = rot + (size_t)s * HEAD_DIM * HEAD_DIM;

    float acc[NROWS];
    #pragma unroll
    for (int n = 0; n < NROWS; n++) acc[n] = 0.0f;

    // Outer-product accumulation: stream rows of R.
    #pragma unroll 8
    for (int h = 0; h < HEAD_DIM; h++) {
        const float r = R[h * HEAD_DIM + t];
        #pragma unroll
        for (int n = 0; n < NROWS; n++)
            acc[n] = fmaf(xs[n][h], r, acc[n]);
    }

    // Write outputs: xq_out then xk_out.
    #pragma unroll
    for (int n = 0; n < NQ; n++)
        out[(n * SEQ_LEN + s) * HEAD_DIM + t] = acc[n];
    out[NQ * SEQ_LEN * HEAD_DIM + s * HEAD_DIM + t] = acc[NQ];
}

extern "C" void kernel_launch(void* const* d_in, const int* in_sizes, int n_in,
                              void* d_out, int out_size) {
    const float* xq  = (const float*)d_in[0];
    const float* xk  = (const float*)d_in[1];
    const float* rot = (const float*)d_in[2];
    float* out = (float*)d_out;

    rotary_kernel<<<SEQ_LEN, HEAD_DIM>>>(xq, xk, rot, out);
}

// round 3
// speedup vs baseline: 1.1956x; 1.1956x over previous
#include <cuda_runtime.h>

// TtLlamaRotary: per-position rotation.
//   xq      [1, 8, 128, 128]   (d_in[0])
//   xk      [1, 1, 128, 128]   (d_in[1])
//   rot_mat [1, 128, 128, 128] (d_in[2])
// out = concat(xq_out [8,128,128], xk_out [1,128,128]) flat float32.
//
// One CTA per seq position s, 1024 threads = 8 h-groups x 128 d-threads.
// Each h-group reduces a 16-wide slice of the K dimension (h) with a fully
// unrolled loop (16 LDGs in flight per warp), partials combined in smem.

#define SEQ_LEN 128
#define HEAD_DIM 128
#define NQ 8
#define NROWS 9        // 8 q heads + 1 k head
#define NGROUPS 8
#define HCHUNK (HEAD_DIM / NGROUPS)   // 16
#define NTHREADS (NGROUPS * HEAD_DIM) // 1024

__global__ __launch_bounds__(NTHREADS, 1)
void rotary_kernel(const float* __restrict__ xq,
                   const float* __restrict__ xk,
                   const float* __restrict__ rot,
                   float* __restrict__ out) {
    const int s   = blockIdx.x;
    const int tid = threadIdx.x;
    const int g   = tid >> 7;        // h-group 0..7
    const int t   = tid & 127;       // output column d

    __shared__ float xs[NROWS][HEAD_DIM];
    __shared__ float part[NGROUPS][NROWS][HEAD_DIM];

    // Stage the 9 input rows for this position (1152 elements, 1024 threads
    // -> strided loop; tid 0..127 take a second element covering the k row).
    for (int idx = tid; idx < NROWS * HEAD_DIM; idx += NTHREADS) {
        const int n = idx >> 7;
        const int d = idx & 127;
        xs[n][d] = (n < NQ) ? xq[(n * SEQ_LEN + s) * HEAD_DIM + d]
                            : xk[s * HEAD_DIM + d];
    }
    __syncthreads();

    const float* __restrict__ R =
        rot + (size_t)s * HEAD_DIM * HEAD_DIM + (size_t)g * HCHUNK * HEAD_DIM + t;

    float acc[NROWS];
    #pragma unroll
    for (int n = 0; n < NROWS; n++) acc[n] = 0.0f;

    // Fully unrolled: 16 independent LDGs batched up front.
    #pragma unroll
    for (int h = 0; h < HCHUNK; h++) {
        const float r = R[h * HEAD_DIM];
        const int hh = g * HCHUNK + h;
        #pragma unroll
        for (int n = 0; n < NROWS; n++)
            acc[n] = fmaf(xs[n][hh], r, acc[n]);
    }

    #pragma unroll
    for (int n = 0; n < NROWS; n++)
        part[g][n][t] = acc[n];
    __syncthreads();

    // Reduce 8 partials per output; 1152 outputs over 1024 threads.
    for (int idx = tid; idx < NROWS * HEAD_DIM; idx += NTHREADS) {
        const int n = idx >> 7;
        const int d = idx & 127;
        float v = 0.0f;
        #pragma unroll
        for (int gg = 0; gg < NGROUPS; gg++)
            v += part[gg][n][d];
        if (n < NQ)
            out[(n * SEQ_LEN + s) * HEAD_DIM + d] = v;
        else
            out[NQ * SEQ_LEN * HEAD_DIM + s * HEAD_DIM + d] = v;
    }
}

extern "C" void kernel_launch(void* const* d_in, const int* in_sizes, int n_in,
                              void* d_out, int out_size) {
    const float* xq  = (const float*)d_in[0];
    const float* xk  = (const float*)d_in[1];
    const float* rot = (const float*)d_in[2];
    float* out = (float*)d_out;

    rotary_kernel<<<SEQ_LEN, NTHREADS>>>(xq, xk, rot, out);
}